// round 1
// baseline (speedup 1.0000x reference)
#include <cuda_runtime.h>
#include <math.h>
#include <stdint.h>

#define NF 65536
#define NB 8
#define JQ 64
#define NSEC 224
#define NCHAN 289
#define LG 768
#define GTAPS 1537          // 2*LG+1
#define KPHI 1024
#define INV_N (1.0f/65536.0f)
#define WINSZ 3332          // 7*256 + 1537 = 3329, padded

// ---------------- static device storage ----------------
static __device__ float2 TW[NF];                 // e^{+2pi i k/N}, double-built
static __device__ float  GF[GTAPS];              // lowpass impulse response
static __device__ float2 d_xf  [  8u*65536u];    // spectra of x
static __device__ float2 d_ping[117440512u];     // 1792*65536
static __device__ float2 d_pong[117440512u];
static __device__ float  d_u1  [ 33554432u];     // 512*65536  |U1| time domain
static __device__ float2 d_u1f [ 33554432u];     // 512*65536  FFT(|U1|)

static __device__ const float2 W16T[16] = {
  { 1.0f, 0.0f},
  { 0.9238795325112867f, 0.3826834323650898f},
  { 0.7071067811865476f, 0.7071067811865476f},
  { 0.3826834323650898f, 0.9238795325112867f},
  { 0.0f, 1.0f},
  {-0.3826834323650898f, 0.9238795325112867f},
  {-0.7071067811865476f, 0.7071067811865476f},
  {-0.9238795325112867f, 0.3826834323650898f},
  {-1.0f, 0.0f},
  {-0.9238795325112867f,-0.3826834323650898f},
  {-0.7071067811865476f,-0.7071067811865476f},
  {-0.3826834323650898f,-0.9238795325112867f},
  { 0.0f,-1.0f},
  { 0.3826834323650898f,-0.9238795325112867f},
  { 0.7071067811865476f,-0.7071067811865476f},
  { 0.9238795325112867f,-0.3826834323650898f}
};

// ---------------- complex helpers ----------------
__device__ __forceinline__ float2 cadd(float2 a, float2 b){ return make_float2(a.x+b.x, a.y+b.y); }
__device__ __forceinline__ float2 csub(float2 a, float2 b){ return make_float2(a.x-b.x, a.y-b.y); }
__device__ __forceinline__ float2 cmul(float2 a, float2 b){ return make_float2(a.x*b.x-a.y*b.y, a.x*b.y+a.y*b.x); }
template<int S> __device__ __forceinline__ float2 mul_i(float2 a){
  return (S>0) ? make_float2(-a.y, a.x) : make_float2(a.y, -a.x);
}
template<int S> __device__ __forceinline__ void dft4(float2&a, float2&b, float2&c, float2&d){
  float2 t0=cadd(a,c), t1=csub(a,c), t2=cadd(b,d), t3=mul_i<S>(csub(b,d));
  a=cadd(t0,t2); c=csub(t0,t2); b=cadd(t1,t3); d=csub(t1,t3);
}
template<int S> __device__ __forceinline__ float2 w16(int m){
  float2 w = W16T[m];
  if (S < 0) w.y = -w.y;
  return w;
}
// natural-order 16-point DFT (sign S: -1 fwd, +1 inv)
template<int S> __device__ __forceinline__ void fft16(float2 v[16]){
  #pragma unroll
  for (int n0=0; n0<4; n0++) dft4<S>(v[n0], v[n0+4], v[n0+8], v[n0+12]);
  #pragma unroll
  for (int n0=1; n0<4; n0++)
    #pragma unroll
    for (int k1=1; k1<4; k1++)
      v[n0+4*k1] = cmul(v[n0+4*k1], w16<S>(n0*k1));
  float2 o[16];
  #pragma unroll
  for (int k1=0; k1<4; k1++){
    float2 a=v[4*k1+0], b=v[4*k1+1], c=v[4*k1+2], d=v[4*k1+3];
    dft4<S>(a,b,c,d);
    o[k1]=a; o[k1+4]=b; o[k1+8]=c; o[k1+12]=d;
  }
  #pragma unroll
  for (int i=0;i<16;i++) v[i]=o[i];
}

// ---------------- setup kernels ----------------
__global__ void k_tw(){
  int k = blockIdx.x*blockDim.x + threadIdx.x;   // 65536 threads
  double a = 6.283185307179586476925286766559 * (double)k / 65536.0;
  TW[k] = make_float2((float)cos(a), (float)sin(a));
}
__global__ void k_g(){
  int i = blockIdx.x*blockDim.x + threadIdx.x;
  if (i >= GTAPS) return;
  int tt = i - LG; if (tt < 0) tt = -tt;
  const float invden = 1.0f/(65536.0f*(0.35f/256.0f));  // 1/(N*sig_phi)
  float acc = 1.0f;                                     // k=0: phi=1
  for (int k=1; k<=KPHI; k++){
    float z = (float)k * invden;
    float p = expf(-0.5f*z*z);
    int m = (k*tt) & 65535;
    acc += 2.0f * p * TW[m].x;
  }
  GF[i] = acc * INV_N;
}

// ---------------- Stockham stage ----------------
// MIN: 0 complex, 1 real(imag=0), 2 xf*psi1/N (first order), 3 u1f*psi2/N (second order)
// MOUT: 0 complex, 1 |.| to float
template<int SIGN, int MIN, int MOUT>
__global__ void __launch_bounds__(256) k_stage(
    const float2* __restrict__ cin, const float* __restrict__ rin,
    float2* __restrict__ cout, float* __restrict__ rout,
    int Ns, int sh)
{
  const int ti = blockIdx.y;
  const int j  = blockIdx.x*256 + threadIdx.x;    // [0,4096)
  float2 v[16];

  if (MIN == 0){
    const float2* p = cin + (size_t)ti*NF + j;
    #pragma unroll
    for (int r=0;r<16;r++) v[r] = p[r*4096];
  } else if (MIN == 1){
    const float* p = rin + (size_t)ti*NF + j;
    #pragma unroll
    for (int r=0;r<16;r++) v[r] = make_float2(p[r*4096], 0.0f);
  } else if (MIN == 2){
    const int b = ti >> 6, ch = ti & 63;
    const float xi   = 0.35f * exp2f(-(float)ch * 0.125f);
    const float invs = 8.0f / xi;
    const float2* p  = cin + (size_t)b*NF;
    #pragma unroll
    for (int r=0;r<16;r++){
      int k = j + r*4096;
      float f = (k < 32768) ? (float)k * INV_N : ((float)k - 65536.0f) * INV_N;
      float z = (f - xi) * invs;
      float g = expf(-0.5f*z*z);
      if (g > 1e-12f){ float2 X = p[k]; float s = g * INV_N; v[r] = make_float2(X.x*s, X.y*s); }
      else v[r] = make_float2(0.0f, 0.0f);
    }
  } else { // MIN == 3
    const int b = ti / NSEC;
    const int s0 = ti - b*NSEC;
    int j2 = 1;
    #pragma unroll
    for (int q=1; q<7; q++) if (s0 >= 4*q*(q+1)) j2 = q+1;
    const int ch = s0 - 4*j2*(j2-1);
    const float xi   = 0.35f * exp2f(-(float)j2);
    const float invs = 1.0f / (0.6f * xi);
    const float2* p  = cin + ((size_t)b*JQ + ch)*NF;
    #pragma unroll
    for (int r=0;r<16;r++){
      int k = j + r*4096;
      float f = (k < 32768) ? (float)k * INV_N : ((float)k - 65536.0f) * INV_N;
      float z = (f - xi) * invs;
      float g = expf(-0.5f*z*z);
      if (g > 1e-12f){ float2 X = p[k]; float s = g * INV_N; v[r] = make_float2(X.x*s, X.y*s); }
      else v[r] = make_float2(0.0f, 0.0f);
    }
  }

  if (Ns > 1){
    const int m = j & (Ns - 1);
    const int step = (NF >> (4 + sh)) * m;
    #pragma unroll
    for (int r=1; r<16; r++){
      float2 w = TW[(r*step) & (NF-1)];
      if (SIGN < 0) w.y = -w.y;
      v[r] = cmul(v[r], w);
    }
  }

  fft16<SIGN>(v);

  const int jd = ((j >> sh) << (sh + 4)) + (j & (Ns - 1));
  if (MOUT == 0){
    float2* p = cout + (size_t)ti*NF + jd;
    #pragma unroll
    for (int r=0;r<16;r++) p[r*Ns] = v[r];
  } else {
    float* p = rout + (size_t)ti*NF + jd;
    #pragma unroll
    for (int r=0;r<16;r++) p[r*Ns] = sqrtf(v[r].x*v[r].x + v[r].y*v[r].y);
  }
}

// ---------------- lowpass conv + log epilogue ----------------
// grid (32, 289, 8), block 256. Each block: 8 outputs (one per warp) of one channel.
__global__ void __launch_bounds__(256) k_conv(
    const float* __restrict__ x, const float* __restrict__ u1,
    const float* __restrict__ u2, float* __restrict__ out)
{
  const int grp = blockIdx.x, c = blockIdx.y, b = blockIdx.z;
  const float* src;
  if (c == 0)       src = x  + (size_t)b*NF;
  else if (c < 65)  src = u1 + ((size_t)b*JQ   + (c-1 ))*NF;
  else              src = u2 + ((size_t)b*NSEC + (c-65))*NF;

  __shared__ float win[WINSZ];
  __shared__ float gs[GTAPS];
  const int tid = threadIdx.x;
  const int w0 = grp*2048 - LG;
  for (int i=tid; i<3329; i+=256) win[i] = src[(w0 + i) & 65535];
  for (int i=tid; i<GTAPS; i+=256) gs[i] = GF[i];
  __syncthreads();

  const int warp = tid >> 5, lane = tid & 31;
  const int off = warp * 256;
  float acc = 0.0f;
  for (int i=lane; i<GTAPS; i+=32) acc += gs[i] * win[off + i];
  #pragma unroll
  for (int d=16; d; d>>=1) acc += __shfl_down_sync(0xffffffffu, acc, d);
  if (lane == 0){
    int n = grp*8 + warp;
    float mag = sqrtf(acc*acc + 1e-8f);
    float val = logf(mag + 1e-8f);
    out[((size_t)b*NCHAN + c)*256 + n] = val;
  }
}

__global__ void k_zero(float* p, int n){
  int i = blockIdx.x*blockDim.x + threadIdx.x;
  if (i < n) p[i] = 0.0f;
}

// ---------------- launch ----------------
extern "C" void kernel_launch(void* const* d_in, const int* in_sizes, int n_in,
                              void* d_out, int out_size)
{
  (void)in_sizes; (void)n_in;
  const float* x = (const float*)d_in[0];
  float* out = (float*)d_out;

  float2 *tw, *xf, *ping, *pong, *u1f;
  float  *u1;
  cudaGetSymbolAddress((void**)&tw,   TW);
  cudaGetSymbolAddress((void**)&xf,   d_xf);
  cudaGetSymbolAddress((void**)&ping, d_ping);
  cudaGetSymbolAddress((void**)&pong, d_pong);
  cudaGetSymbolAddress((void**)&u1,   d_u1);
  cudaGetSymbolAddress((void**)&u1f,  d_u1f);
  (void)tw;
  float* u2 = (float*)pong;   // |U2| aliases pong (written in last SO stage, read by conv)

  k_tw<<<256, 256>>>();
  k_g <<<7,   256>>>();

  // forward FFT of x: 8 transforms
  k_stage<-1,1,0><<<dim3(16,8),   256>>>(nullptr, x,    ping, nullptr,    1, 0);
  k_stage<-1,0,0><<<dim3(16,8),   256>>>(ping, nullptr, pong, nullptr,   16, 4);
  k_stage<-1,0,0><<<dim3(16,8),   256>>>(pong, nullptr, ping, nullptr,  256, 8);
  k_stage<-1,0,0><<<dim3(16,8),   256>>>(ping, nullptr, xf,   nullptr, 4096,12);

  // first-order IFFT(xf*psi1)/N -> |U1|: 512 transforms
  k_stage< 1,2,0><<<dim3(16,512), 256>>>(xf,   nullptr, ping, nullptr,    1, 0);
  k_stage< 1,0,0><<<dim3(16,512), 256>>>(ping, nullptr, pong, nullptr,   16, 4);
  k_stage< 1,0,0><<<dim3(16,512), 256>>>(pong, nullptr, ping, nullptr,  256, 8);
  k_stage< 1,0,1><<<dim3(16,512), 256>>>(ping, nullptr, nullptr, u1,   4096,12);

  // forward FFT of |U1|: 512 transforms
  k_stage<-1,1,0><<<dim3(16,512), 256>>>(nullptr, u1,   ping, nullptr,    1, 0);
  k_stage<-1,0,0><<<dim3(16,512), 256>>>(ping, nullptr, pong, nullptr,   16, 4);
  k_stage<-1,0,0><<<dim3(16,512), 256>>>(pong, nullptr, ping, nullptr,  256, 8);
  k_stage<-1,0,0><<<dim3(16,512), 256>>>(ping, nullptr, u1f,  nullptr, 4096,12);

  // second-order IFFT(U1f*psi2)/N -> |U2|: 1792 transforms
  k_stage< 1,3,0><<<dim3(16,1792),256>>>(u1f,  nullptr, ping, nullptr,    1, 0);
  k_stage< 1,0,0><<<dim3(16,1792),256>>>(ping, nullptr, pong, nullptr,   16, 4);
  k_stage< 1,0,0><<<dim3(16,1792),256>>>(pong, nullptr, ping, nullptr,  256, 8);
  k_stage< 1,0,1><<<dim3(16,1792),256>>>(ping, nullptr, nullptr, u2,   4096,12);

  // lowpass conv + subsample + log  (S0 from x, S1 from |U1|, S2 from |U2|)
  k_conv<<<dim3(32, NCHAN, NB), 256>>>(x, u1, u2, out);

  // imaginary half = zeros
  int half = out_size / 2;
  k_zero<<<(half + 255)/256, 256>>>(out + half, half);
}